// round 1
// baseline (speedup 1.0000x reference)
#include <cuda_runtime.h>
#include <math.h>

// Problem constants
#define BB    2
#define NH    16
#define TQ    2048
#define TP    2048
#define TKV   4096
#define DK    64
#define DM    1024
#define MROWS (BB*TQ)          // 4096

// Scratch (device globals: allocation-free)
__device__ float g_Q[(size_t)BB*NH*TQ*DK];     // [B,H,TQ,DK]  16 MB
__device__ float g_att[(size_t)BB*TQ*DM];      // [B,TQ,DM]    16 MB

// ---------------------------------------------------------------------------
// Copy past_K / past_V ([B,H,TP,DK]) into cache output ([B,H,TKV,DK], rows 0..TP)
// ---------------------------------------------------------------------------
__global__ void copy_past_kernel(const float4* __restrict__ src, float4* __restrict__ dst) {
    const int total = BB*NH*TP*DK/4;            // 1,048,576
    int i = blockIdx.x * blockDim.x + threadIdx.x;
    if (i < total) {
        int bh  = i >> 15;                      // TP*DK/4 = 32768
        int rem = i & 32767;
        dst[(size_t)bh * (TKV*DK/4) + rem] = src[i];
    }
}

// ---------------------------------------------------------------------------
// C = A(M,K) @ W(N,K)^T + bias, fp32, 128x128x8 tiling, 256 threads, 8x8 micro.
// mode 0: C row-major [M,N]
// mode 1: scatter to [B,H,TQ,DK]            (Q scratch)
// mode 2: scatter to [B,H,TKV,DK] at +TP    (K/V cache)
// ---------------------------------------------------------------------------
__global__ __launch_bounds__(256) void gemm_nt(const float* __restrict__ A,
                                               const float* __restrict__ W,
                                               const float* __restrict__ bias,
                                               float* __restrict__ C,
                                               int mode) {
    const int K = DM, N = DM;
    __shared__ float As[8][128];
    __shared__ float Bs[8][128];

    const int tid = threadIdx.x;
    const int tx = tid & 15;        // 0..15 -> n
    const int ty = tid >> 4;        // 0..15 -> m
    const int mBase = blockIdx.y * 128;
    const int nBase = blockIdx.x * 128;

    float acc[8][8];
    #pragma unroll
    for (int i = 0; i < 8; i++)
        #pragma unroll
        for (int j = 0; j < 8; j++) acc[i][j] = 0.f;

    const int lrow = tid >> 1;          // 0..127
    const int lk   = (tid & 1) * 4;     // 0 or 4
    const float* Aptr = A + (size_t)(mBase + lrow) * K + lk;
    const float* Wptr = W + (size_t)(nBase + lrow) * K + lk;

    for (int kb = 0; kb < K; kb += 8) {
        float4 av = *(const float4*)(Aptr + kb);
        float4 bv = *(const float4*)(Wptr + kb);
        As[lk+0][lrow] = av.x; As[lk+1][lrow] = av.y;
        As[lk+2][lrow] = av.z; As[lk+3][lrow] = av.w;
        Bs[lk+0][lrow] = bv.x; Bs[lk+1][lrow] = bv.y;
        Bs[lk+2][lrow] = bv.z; Bs[lk+3][lrow] = bv.w;
        __syncthreads();

        #pragma unroll
        for (int kk = 0; kk < 8; kk++) {
            float a[8], b[8];
            #pragma unroll
            for (int i = 0; i < 8; i++) a[i] = As[kk][ty*8 + i];
            #pragma unroll
            for (int j = 0; j < 8; j++) b[j] = Bs[kk][tx*8 + j];
            #pragma unroll
            for (int i = 0; i < 8; i++)
                #pragma unroll
                for (int j = 0; j < 8; j++)
                    acc[i][j] = fmaf(a[i], b[j], acc[i][j]);
        }
        __syncthreads();
    }

    #pragma unroll
    for (int i = 0; i < 8; i++) {
        int m = mBase + ty*8 + i;
        int b_ = m / TQ;
        int t_ = m % TQ;
        #pragma unroll
        for (int j = 0; j < 8; j++) {
            int n = nBase + tx*8 + j;
            float v = acc[i][j] + bias[n];
            if (mode == 0) {
                C[(size_t)m * N + n] = v;
            } else {
                int h = n >> 6, d = n & 63;
                if (mode == 1)
                    C[(((size_t)(b_*NH + h))*TQ + t_)*DK + d] = v;
                else
                    C[(((size_t)(b_*NH + h))*TKV + TP + t_)*DK + d] = v;
            }
        }
    }
}

// ---------------------------------------------------------------------------
// Flash attention, fp32. One block = 64 queries of one (b,h). 256 threads:
// thread t -> query row qr = t>>2, dim-group cg = t&3 (16 of 64 dims).
// Online softmax; causal => full tiles then exactly one masked tile.
// ---------------------------------------------------------------------------
__global__ __launch_bounds__(256) void attn_kernel(const float* __restrict__ Kc,
                                                   const float* __restrict__ Vc) {
    __shared__ float Ks[64*64];
    __shared__ float Vs[64*64];

    const int tid = threadIdx.x;
    const int qb  = blockIdx.x;        // 0..31
    const int bh  = blockIdx.y;        // 0..31
    const int qr  = tid >> 2;
    const int cg  = tid & 3;
    const int qg  = qb*64 + qr;        // global query index in [0,TQ)

    // Load Q row slice, pre-scaled by 1/sqrt(dk)
    const float* qp = g_Q + ((size_t)bh*TQ + qg)*DK + cg*16;
    float q[16];
    #pragma unroll
    for (int i = 0; i < 16; i += 4) {
        float4 v = *(const float4*)(qp + i);
        q[i+0] = v.x*0.125f; q[i+1] = v.y*0.125f;
        q[i+2] = v.z*0.125f; q[i+3] = v.w*0.125f;
    }

    float o[16];
    #pragma unroll
    for (int j = 0; j < 16; j++) o[j] = 0.f;
    float m = -INFINITY, l = 0.f;

    const int lane = tid & 31;
    const unsigned gmask = 0xFu << (lane & 28);

    const int nfull = 32 + qb;                       // tiles 0..nfull-1 full, tile nfull masked
    const float* Kbase = Kc + (size_t)bh*TKV*DK;
    const float* Vbase = Vc + (size_t)bh*TKV*DK;

    for (int kt = 0; kt <= nfull; ++kt) {
        const float4* kg = (const float4*)(Kbase + (size_t)kt*64*DK);
        const float4* vg = (const float4*)(Vbase + (size_t)kt*64*DK);
        float4* ks4 = (float4*)Ks;
        float4* vs4 = (float4*)Vs;
        #pragma unroll
        for (int i = 0; i < 4; i++) {
            int idx = tid + 256*i;
            ks4[idx] = kg[idx];
            vs4[idx] = vg[idx];
        }
        __syncthreads();

        const int kend = (kt == nfull) ? (qr + 1) : 64;
        for (int k = 0; k < kend; ++k) {
            const float* krow = Ks + k*64 + cg*16;
            float s = 0.f;
            #pragma unroll
            for (int i = 0; i < 16; i += 4) {
                float4 kv = *(const float4*)(krow + i);
                s = fmaf(q[i+0], kv.x, s);
                s = fmaf(q[i+1], kv.y, s);
                s = fmaf(q[i+2], kv.z, s);
                s = fmaf(q[i+3], kv.w, s);
            }
            s += __shfl_xor_sync(gmask, s, 1);
            s += __shfl_xor_sync(gmask, s, 2);

            if (s > m) {
                float corr = __expf(m - s);
                m = s;
                l *= corr;
                #pragma unroll
                for (int j = 0; j < 16; j++) o[j] *= corr;
            }
            float p = __expf(s - m);
            l += p;

            const float* vrow = Vs + k*64 + cg*16;
            #pragma unroll
            for (int j = 0; j < 16; j += 4) {
                float4 vv = *(const float4*)(vrow + j);
                o[j+0] = fmaf(p, vv.x, o[j+0]);
                o[j+1] = fmaf(p, vv.y, o[j+1]);
                o[j+2] = fmaf(p, vv.z, o[j+2]);
                o[j+3] = fmaf(p, vv.w, o[j+3]);
            }
        }
        __syncthreads();
    }

    const float inv = 1.f / l;
    const int b_ = bh >> 4, h_ = bh & 15;
    float* op = g_att + ((size_t)b_*TQ + qg)*DM + h_*DK + cg*16;
    #pragma unroll
    for (int j = 0; j < 16; j += 4) {
        float4 v;
        v.x = o[j+0]*inv; v.y = o[j+1]*inv;
        v.z = o[j+2]*inv; v.w = o[j+3]*inv;
        *(float4*)(op + j) = v;
    }
}

// ---------------------------------------------------------------------------
// Launch
// ---------------------------------------------------------------------------
extern "C" void kernel_launch(void* const* d_in, const int* in_sizes, int n_in,
                              void* d_out, int out_size) {
    const float* query = (const float*)d_in[0];
    const float* key   = (const float*)d_in[1];
    const float* value = (const float*)d_in[2];
    const float* pastK = (const float*)d_in[3];
    const float* pastV = (const float*)d_in[4];
    // d_in[5] = mask (causal; computed analytically, not read)
    const float* Wq = (const float*)d_in[6];
    const float* bq = (const float*)d_in[7];
    const float* Wk = (const float*)d_in[8];
    const float* bk = (const float*)d_in[9];
    const float* Wv = (const float*)d_in[10];
    const float* bv = (const float*)d_in[11];
    const float* Wo = (const float*)d_in[12];
    const float* bo = (const float*)d_in[13];

    float* out  = (float*)d_out;                          // [B,TQ,DM]
    float* Kout = out  + (size_t)BB*TQ*DM;                // [B,H,TKV,DK]
    float* Vout = Kout + (size_t)BB*NH*TKV*DK;            // [B,H,TKV,DK]

    float *pQ, *pAtt;
    cudaGetSymbolAddress((void**)&pQ, g_Q);
    cudaGetSymbolAddress((void**)&pAtt, g_att);

    const int copyN = BB*NH*TP*DK/4;
    copy_past_kernel<<<(copyN + 255)/256, 256>>>((const float4*)pastK, (float4*)Kout);
    copy_past_kernel<<<(copyN + 255)/256, 256>>>((const float4*)pastV, (float4*)Vout);

    dim3 gg(DM/128, MROWS/128);   // (8, 32)
    gemm_nt<<<gg, 256>>>(query, Wq, bq, pQ,   1);
    gemm_nt<<<gg, 256>>>(key,   Wk, bk, Kout, 2);
    gemm_nt<<<gg, 256>>>(value, Wv, bv, Vout, 2);

    attn_kernel<<<dim3(TQ/64, BB*NH), 256>>>(Kout, Vout);

    gemm_nt<<<gg, 256>>>(pAtt, Wo, bo, out, 0);
}

// round 3
// speedup vs baseline: 1.0001x; 1.0001x over previous
#include <cuda_runtime.h>
#include <math.h>

// Problem constants
#define BB    2
#define NH    16
#define TQ    2048
#define TP    2048
#define TKV   4096
#define DK    64
#define DM    1024
#define MROWS (BB*TQ)          // 4096

// Scratch (device globals: allocation-free)
__device__ float g_Q[(size_t)BB*NH*TQ*DK];     // [B,H,TQ,DK]  16 MB
__device__ float g_att[(size_t)BB*TQ*DM];      // [B,TQ,DM]    16 MB

// ---------------------------------------------------------------------------
// Copy past_K / past_V ([B,H,TP,DK]) into cache output ([B,H,TKV,DK], rows 0..TP)
// ---------------------------------------------------------------------------
__global__ void copy_past_kernel(const float4* __restrict__ src, float4* __restrict__ dst) {
    const int total = BB*NH*TP*DK/4;            // 1,048,576
    int i = blockIdx.x * blockDim.x + threadIdx.x;
    if (i < total) {
        int bh  = i >> 15;                      // TP*DK/4 = 32768
        int rem = i & 32767;
        dst[(size_t)bh * (TKV*DK/4) + rem] = src[i];
    }
}

// ---------------------------------------------------------------------------
// C = A(M,K) @ W(N,K)^T + bias, fp32, 128x128x8 tiling, 256 threads, 8x8 micro.
// mode 0: C row-major [M,N]
// mode 1: scatter to [B,H,TQ,DK]            (Q scratch)
// mode 2: scatter to [B,H,TKV,DK] at +TP    (K/V cache)
// ---------------------------------------------------------------------------
__global__ __launch_bounds__(256) void gemm_nt(const float* __restrict__ A,
                                               const float* __restrict__ W,
                                               const float* __restrict__ bias,
                                               float* __restrict__ C,
                                               int mode) {
    const int K = DM, N = DM;
    __shared__ float As[8][128];
    __shared__ float Bs[8][128];

    const int tid = threadIdx.x;
    const int tx = tid & 15;        // 0..15 -> n
    const int ty = tid >> 4;        // 0..15 -> m
    const int mBase = blockIdx.y * 128;
    const int nBase = blockIdx.x * 128;

    float acc[8][8];
    #pragma unroll
    for (int i = 0; i < 8; i++)
        #pragma unroll
        for (int j = 0; j < 8; j++) acc[i][j] = 0.f;

    const int lrow = tid >> 1;          // 0..127
    const int lk   = (tid & 1) * 4;     // 0 or 4
    const float* Aptr = A + (size_t)(mBase + lrow) * K + lk;
    const float* Wptr = W + (size_t)(nBase + lrow) * K + lk;

    for (int kb = 0; kb < K; kb += 8) {
        float4 av = *(const float4*)(Aptr + kb);
        float4 bv = *(const float4*)(Wptr + kb);
        As[lk+0][lrow] = av.x; As[lk+1][lrow] = av.y;
        As[lk+2][lrow] = av.z; As[lk+3][lrow] = av.w;
        Bs[lk+0][lrow] = bv.x; Bs[lk+1][lrow] = bv.y;
        Bs[lk+2][lrow] = bv.z; Bs[lk+3][lrow] = bv.w;
        __syncthreads();

        #pragma unroll
        for (int kk = 0; kk < 8; kk++) {
            float a[8], b[8];
            #pragma unroll
            for (int i = 0; i < 8; i++) a[i] = As[kk][ty*8 + i];
            #pragma unroll
            for (int j = 0; j < 8; j++) b[j] = Bs[kk][tx*8 + j];
            #pragma unroll
            for (int i = 0; i < 8; i++)
                #pragma unroll
                for (int j = 0; j < 8; j++)
                    acc[i][j] = fmaf(a[i], b[j], acc[i][j]);
        }
        __syncthreads();
    }

    #pragma unroll
    for (int i = 0; i < 8; i++) {
        int m = mBase + ty*8 + i;
        int b_ = m / TQ;
        int t_ = m % TQ;
        #pragma unroll
        for (int j = 0; j < 8; j++) {
            int n = nBase + tx*8 + j;
            float v = acc[i][j] + bias[n];
            if (mode == 0) {
                C[(size_t)m * N + n] = v;
            } else {
                int h = n >> 6, d = n & 63;
                if (mode == 1)
                    C[(((size_t)(b_*NH + h))*TQ + t_)*DK + d] = v;
                else
                    C[(((size_t)(b_*NH + h))*TKV + TP + t_)*DK + d] = v;
            }
        }
    }
}

// ---------------------------------------------------------------------------
// Flash attention, fp32. One block = 64 queries of one (b,h). 256 threads:
// thread t -> query row qr = t>>2, dim-group cg = t&3 (16 of 64 dims).
// Online softmax; causal => full tiles then exactly one masked tile.
// ---------------------------------------------------------------------------
__global__ __launch_bounds__(256) void attn_kernel(const float* __restrict__ Kc,
                                                   const float* __restrict__ Vc) {
    __shared__ float Ks[64*64];
    __shared__ float Vs[64*64];

    const int tid = threadIdx.x;
    const int qb  = blockIdx.x;        // 0..31
    const int bh  = blockIdx.y;        // 0..31
    const int qr  = tid >> 2;
    const int cg  = tid & 3;
    const int qg  = qb*64 + qr;        // global query index in [0,TQ)

    // Load Q row slice, pre-scaled by 1/sqrt(dk)
    const float* qp = g_Q + ((size_t)bh*TQ + qg)*DK + cg*16;
    float q[16];
    #pragma unroll
    for (int i = 0; i < 16; i += 4) {
        float4 v = *(const float4*)(qp + i);
        q[i+0] = v.x*0.125f; q[i+1] = v.y*0.125f;
        q[i+2] = v.z*0.125f; q[i+3] = v.w*0.125f;
    }

    float o[16];
    #pragma unroll
    for (int j = 0; j < 16; j++) o[j] = 0.f;
    float m = -INFINITY, l = 0.f;

    const int lane = tid & 31;
    const unsigned gmask = 0xFu << (lane & 28);

    const int nfull = 32 + qb;                       // tiles 0..nfull-1 full, tile nfull masked
    const float* Kbase = Kc + (size_t)bh*TKV*DK;
    const float* Vbase = Vc + (size_t)bh*TKV*DK;

    for (int kt = 0; kt <= nfull; ++kt) {
        const float4* kg = (const float4*)(Kbase + (size_t)kt*64*DK);
        const float4* vg = (const float4*)(Vbase + (size_t)kt*64*DK);
        float4* ks4 = (float4*)Ks;
        float4* vs4 = (float4*)Vs;
        #pragma unroll
        for (int i = 0; i < 4; i++) {
            int idx = tid + 256*i;
            ks4[idx] = kg[idx];
            vs4[idx] = vg[idx];
        }
        __syncthreads();

        const int kend = (kt == nfull) ? (qr + 1) : 64;
        for (int k = 0; k < kend; ++k) {
            const float* krow = Ks + k*64 + cg*16;
            float s = 0.f;
            #pragma unroll
            for (int i = 0; i < 16; i += 4) {
                float4 kv = *(const float4*)(krow + i);
                s = fmaf(q[i+0], kv.x, s);
                s = fmaf(q[i+1], kv.y, s);
                s = fmaf(q[i+2], kv.z, s);
                s = fmaf(q[i+3], kv.w, s);
            }
            s += __shfl_xor_sync(gmask, s, 1);
            s += __shfl_xor_sync(gmask, s, 2);

            if (s > m) {
                float corr = __expf(m - s);
                m = s;
                l *= corr;
                #pragma unroll
                for (int j = 0; j < 16; j++) o[j] *= corr;
            }
            float p = __expf(s - m);
            l += p;

            const float* vrow = Vs + k*64 + cg*16;
            #pragma unroll
            for (int j = 0; j < 16; j += 4) {
                float4 vv = *(const float4*)(vrow + j);
                o[j+0] = fmaf(p, vv.x, o[j+0]);
                o[j+1] = fmaf(p, vv.y, o[j+1]);
                o[j+2] = fmaf(p, vv.z, o[j+2]);
                o[j+3] = fmaf(p, vv.w, o[j+3]);
            }
        }
        __syncthreads();
    }

    const float inv = 1.f / l;
    const int b_ = bh >> 4, h_ = bh & 15;
    float* op = g_att + ((size_t)b_*TQ + qg)*DM + h_*DK + cg*16;
    #pragma unroll
    for (int j = 0; j < 16; j += 4) {
        float4 v;
        v.x = o[j+0]*inv; v.y = o[j+1]*inv;
        v.z = o[j+2]*inv; v.w = o[j+3]*inv;
        *(float4*)(op + j) = v;
    }
}

// ---------------------------------------------------------------------------
// Launch
// ---------------------------------------------------------------------------
extern "C" void kernel_launch(void* const* d_in, const int* in_sizes, int n_in,
                              void* d_out, int out_size) {
    const float* query = (const float*)d_in[0];
    const float* key   = (const float*)d_in[1];
    const float* value = (const float*)d_in[2];
    const float* pastK = (const float*)d_in[3];
    const float* pastV = (const float*)d_in[4];
    // d_in[5] = mask (causal; computed analytically, not read)
    const float* Wq = (const float*)d_in[6];
    const float* bq = (const float*)d_in[7];
    const float* Wk = (const float*)d_in[8];
    const float* bk = (const float*)d_in[9];
    const float* Wv = (const float*)d_in[10];
    const float* bv = (const float*)d_in[11];
    const float* Wo = (const float*)d_in[12];
    const float* bo = (const float*)d_in[13];

    float* out  = (float*)d_out;                          // [B,TQ,DM]
    float* Kout = out  + (size_t)BB*TQ*DM;                // [B,H,TKV,DK]
    float* Vout = Kout + (size_t)BB*NH*TKV*DK;            // [B,H,TKV,DK]

    float *pQ, *pAtt;
    cudaGetSymbolAddress((void**)&pQ, g_Q);
    cudaGetSymbolAddress((void**)&pAtt, g_att);

    const int copyN = BB*NH*TP*DK/4;
    copy_past_kernel<<<(copyN + 255)/256, 256>>>((const float4*)pastK, (float4*)Kout);
    copy_past_kernel<<<(copyN + 255)/256, 256>>>((const float4*)pastV, (float4*)Vout);

    dim3 gg(DM/128, MROWS/128);   // (8, 32)
    gemm_nt<<<gg, 256>>>(query, Wq, bq, pQ,   1);
    gemm_nt<<<gg, 256>>>(key,   Wk, bk, Kout, 2);
    gemm_nt<<<gg, 256>>>(value, Wv, bv, Vout, 2);

    attn_kernel<<<dim3(TQ/64, BB*NH), 256>>>(Kout, Vout);

    gemm_nt<<<gg, 256>>>(pAtt, Wo, bo, out, 0);
}